// round 15
// baseline (speedup 1.0000x reference)
#include <cuda_runtime.h>

// Problem constants (fixed by the reference):
//   N=100000 nodes, E=1600000 edges, IN=128, HID=64, OUT=8, B=16384
// NOTE: reference uses jnp.int64 but JAX x64 is disabled -> edge_index/idx are int32.
#define N_MAX 100000
#define E_MAX 1600000

// ---------------- scratch (device globals; no allocation allowed) ----------
__device__ __align__(256) int   g_deg[N_MAX];
__device__ __align__(256) int   g_rowstart[N_MAX + 1];
__device__ __align__(256) int   g_cursor[N_MAX];
__device__ __align__(256) int   g_srclist[E_MAX];
__device__ __align__(256) int   g_blocksums[512];
__device__ __align__(256) float g_yl[(size_t)N_MAX * 64];  // x@W1_l (gathered: compact)
__device__ __align__(256) float g_yr[(size_t)N_MAX * 64];  // x@W1_r (per-node only)
__device__ __align__(256) float g_h[(size_t)N_MAX * 64];   // layer-1 activations
__device__ __align__(256) float g_z[(size_t)N_MAX * 8];    // h @ W2_l

// ---------------- stream/event for forked capture (created pre-main) --------
static cudaStream_t g_s2 = 0;
static cudaEvent_t  g_ev_fork = 0, g_ev_join = 0;
namespace {
struct StreamInit {
    StreamInit() {
        cudaStreamCreateWithFlags(&g_s2, cudaStreamNonBlocking);
        cudaEventCreateWithFlags(&g_ev_fork, cudaEventDisableTiming);
        cudaEventCreateWithFlags(&g_ev_join, cudaEventDisableTiming);
    }
};
static StreamInit g_stream_init;
}

// ---------------- CSR build --------------------------------------------------
__global__ void hist_kernel(const int* __restrict__ dst, int e) {
    int i = blockIdx.x * blockDim.x + threadIdx.x;
    if (i < e) atomicAdd(&g_deg[dst[i]], 1);
}

// per-block exclusive scan over 256 elements
__global__ void __launch_bounds__(256) scan_block_kernel(int n) {
    __shared__ int s[256];
    int i = blockIdx.x * 256 + threadIdx.x;
    int v = (i < n) ? g_deg[i] : 0;
    s[threadIdx.x] = v;
    __syncthreads();
#pragma unroll
    for (int off = 1; off < 256; off <<= 1) {
        int t = 0;
        if ((int)threadIdx.x >= off) t = s[threadIdx.x - off];
        __syncthreads();
        if ((int)threadIdx.x >= off) s[threadIdx.x] += t;
        __syncthreads();
    }
    if (i < n) g_rowstart[i] = s[threadIdx.x] - v;  // exclusive within block
    if (threadIdx.x == 255) g_blocksums[blockIdx.x] = s[255];
}

// add_offsets with inlined block-sum prefix: each block reduces
// g_blocksums[0..blockIdx) itself (<=391 values), then offsets its 256 rows.
__global__ void __launch_bounds__(256) add_offsets_kernel(int n, int e) {
    __shared__ int red[256];
    int b = blockIdx.x;
    int t = threadIdx.x;
    int part = 0;
    for (int i = t; i < b; i += 256) part += g_blocksums[i];
    red[t] = part;
    __syncthreads();
#pragma unroll
    for (int off = 128; off > 0; off >>= 1) {
        if (t < off) red[t] += red[t + off];
        __syncthreads();
    }
    int base = red[0];
    int i = b * 256 + t;
    if (i < n) {
        int r = g_rowstart[i] + base;
        g_rowstart[i] = r;
        g_cursor[i]   = r;
    }
    if (b == 0 && t == 0) g_rowstart[n] = e;
}

__global__ void scatter_kernel(const int* __restrict__ src,
                               const int* __restrict__ dst, int e) {
    int i = blockIdx.x * blockDim.x + threadIdx.x;
    if (i < e) {
        int d = dst[i];
        int p = atomicAdd(&g_cursor[d], 1);
        g_srclist[p] = src[i];
    }
}

// ---------------- GEMM1: [yl|yr] = x @ [W1_l | W1_r]  (N x 128 @ 128 x 128) -
// Tile: BM=128 rows, BN=128 cols, BK=16. 256 threads; each thread: 8x8 outputs.
// Single-buffered smem; scalar FFMA (measured at its pipe floor, 88.8us).
__global__ void __launch_bounds__(256) gemm1_kernel(const float* __restrict__ x,
                                                    const float* __restrict__ Wl,
                                                    const float* __restrict__ Wr,
                                                    int n) {
    __shared__ __align__(16) float xs[16][132];  // k-major, padded: 8448 B
    __shared__ __align__(16) float ws[16][128];  // 8192 B
    int tid = threadIdx.x;
    int row0 = blockIdx.x * 128;
    int tx = tid & 15;  // cols [tx*8, tx*8+8)
    int ty = tid >> 4;  // rows [ty*8, ty*8+8)

    float acc[8][8];
#pragma unroll
    for (int r = 0; r < 8; r++)
#pragma unroll
        for (int c = 0; c < 8; c++) acc[r][c] = 0.0f;

    int xr0 = tid >> 2;  // 0..63
    int xc4 = tid & 3;   // float4 slot within 16-wide k slab
    int wk0 = tid >> 5;  // 0..7
    int wc4 = tid & 31;  // 0..31 (c4<16 -> Wl, else Wr)

    for (int kb = 0; kb < 128; kb += 16) {
        // load x tile 128x16 -> xs[k][row] (transposed store)
#pragma unroll
        for (int it = 0; it < 2; it++) {
            int row = xr0 + it * 64;
            int gr = row0 + row;
            float4 v = make_float4(0.f, 0.f, 0.f, 0.f);
            if (gr < n) v = *(const float4*)(x + (size_t)gr * 128 + kb + xc4 * 4);
            xs[xc4 * 4 + 0][row] = v.x;
            xs[xc4 * 4 + 1][row] = v.y;
            xs[xc4 * 4 + 2][row] = v.z;
            xs[xc4 * 4 + 3][row] = v.w;
        }
        // load W tile 16x128 (cols 0:64 = Wl, 64:128 = Wr)
#pragma unroll
        for (int it = 0; it < 2; it++) {
            int k = wk0 + it * 8;
            float4 v;
            if (wc4 < 16) v = *(const float4*)(Wl + (kb + k) * 64 + wc4 * 4);
            else          v = *(const float4*)(Wr + (kb + k) * 64 + (wc4 - 16) * 4);
            *(float4*)&ws[k][wc4 * 4] = v;
        }
        __syncthreads();
#pragma unroll
        for (int k = 0; k < 16; k++) {
            float4 a0 = *(float4*)&xs[k][ty * 8];
            float4 a1 = *(float4*)&xs[k][ty * 8 + 4];
            float4 b0 = *(float4*)&ws[k][tx * 8];
            float4 b1 = *(float4*)&ws[k][tx * 8 + 4];
            float av[8] = {a0.x, a0.y, a0.z, a0.w, a1.x, a1.y, a1.z, a1.w};
            float bv[8] = {b0.x, b0.y, b0.z, b0.w, b1.x, b1.y, b1.z, b1.w};
#pragma unroll
            for (int r = 0; r < 8; r++)
#pragma unroll
                for (int c = 0; c < 8; c++) acc[r][c] += av[r] * bv[c];
        }
        __syncthreads();
    }
    // epilogue: cols 0:64 -> g_yl, cols 64:128 -> g_yr (compact 64-float rows)
    float* dstbase = (tx < 8) ? g_yl : g_yr;
    int colbase = (tx < 8) ? tx * 8 : tx * 8 - 64;
#pragma unroll
    for (int r = 0; r < 8; r++) {
        int gr = row0 + ty * 8 + r;
        if (gr < n) {
            *(float4*)(dstbase + (size_t)gr * 64 + colbase) =
                make_float4(acc[r][0], acc[r][1], acc[r][2], acc[r][3]);
            *(float4*)(dstbase + (size_t)gr * 64 + colbase + 4) =
                make_float4(acc[r][4], acc[r][5], acc[r][6], acc[r][7]);
        }
    }
}

// ---------------- layer 1 combine + z -----------------------------------
// h = dropout(relu(agg/deg + y_r + b1)); z = h @ W2_l (warp butterfly reduce).
// One warp per node: two 16-lane halves process alternating edges, each lane
// loads float4 (4 dims). Halves merged by xor-16 butterfly.
__global__ void __launch_bounds__(256) layer1_kernel(const float* __restrict__ b1,
                                                     const float* __restrict__ mask,
                                                     const float* __restrict__ W2l,
                                                     int n) {
    __shared__ __align__(16) float w2[512];
    __shared__ float b1s[64];
    for (int i = threadIdx.x; i < 512; i += 256) w2[i] = W2l[i];
    if (threadIdx.x < 64) b1s[threadIdx.x] = b1[threadIdx.x];
    __syncthreads();

    int node = blockIdx.x * 8 + (threadIdx.x >> 5);
    int lane = threadIdx.x & 31;
    int eh = lane >> 4;        // edge-parity half (0/1)
    int l16 = lane & 15;       // lane within half
    int d = l16 * 4;           // feature dims [d, d+4)
    if (node >= n) return;
    int s = g_rowstart[node];
    int epos = g_rowstart[node + 1];

    float4 a0 = make_float4(0.f, 0.f, 0.f, 0.f);
    float4 a1 = make_float4(0.f, 0.f, 0.f, 0.f);
    int e = s + eh;
    for (; e + 2 < epos; e += 4) {
        int s0 = g_srclist[e];
        int s1 = g_srclist[e + 2];
        float4 v0 = *(const float4*)(g_yl + (size_t)s0 * 64 + d);
        float4 v1 = *(const float4*)(g_yl + (size_t)s1 * 64 + d);
        a0.x += v0.x; a0.y += v0.y; a0.z += v0.z; a0.w += v0.w;
        a1.x += v1.x; a1.y += v1.y; a1.z += v1.z; a1.w += v1.w;
    }
    if (e < epos) {
        float4 v = *(const float4*)(g_yl + (size_t)g_srclist[e] * 64 + d);
        a0.x += v.x; a0.y += v.y; a0.z += v.z; a0.w += v.w;
    }
    float sx = a0.x + a1.x, sy = a0.y + a1.y, sz = a0.z + a1.z, sw = a0.w + a1.w;
    // merge the two halves
    sx += __shfl_xor_sync(0xffffffffu, sx, 16);
    sy += __shfl_xor_sync(0xffffffffu, sy, 16);
    sz += __shfl_xor_sync(0xffffffffu, sz, 16);
    sw += __shfl_xor_sync(0xffffffffu, sw, 16);

    float inv = 1.0f / fmaxf((float)(epos - s), 1.0f);
    float4 yr = *(const float4*)(g_yr + (size_t)node * 64 + d);
    float4 mk = *(const float4*)(mask + (size_t)node * 64 + d);
    float hx = fmaxf(sx * inv + yr.x + b1s[d + 0], 0.0f);
    float hy = fmaxf(sy * inv + yr.y + b1s[d + 1], 0.0f);
    float hz = fmaxf(sz * inv + yr.z + b1s[d + 2], 0.0f);
    float hw = fmaxf(sw * inv + yr.w + b1s[d + 3], 0.0f);
    hx = (mk.x > 0.5f) ? hx * 2.0f : 0.0f;
    hy = (mk.y > 0.5f) ? hy * 2.0f : 0.0f;
    hz = (mk.z > 0.5f) ? hz * 2.0f : 0.0f;
    hw = (mk.w > 0.5f) ? hw * 2.0f : 0.0f;
    if (eh == 0)
        *(float4*)(g_h + (size_t)node * 64 + d) = make_float4(hx, hy, hz, hw);

    // z = h @ W2_l : per-lane partials over 4 dims, butterfly within 16-group
    float zacc[8];
#pragma unroll
    for (int j = 0; j < 8; j++)
        zacc[j] = hx * w2[(d + 0) * 8 + j] + hy * w2[(d + 1) * 8 + j]
                + hz * w2[(d + 2) * 8 + j] + hw * w2[(d + 3) * 8 + j];
#pragma unroll
    for (int off = 8; off > 0; off >>= 1)
#pragma unroll
        for (int j = 0; j < 8; j++)
            zacc[j] += __shfl_xor_sync(0xffffffffu, zacc[j], off);
    if (lane == 0) {
        float4* zp = (float4*)(g_z + (size_t)node * 8);
        zp[0] = make_float4(zacc[0], zacc[1], zacc[2], zacc[3]);
        zp[1] = make_float4(zacc[4], zacc[5], zacc[6], zacc[7]);
    }
}

// ---------------- output: out[b] = agg2(idx[b])/deg + h[idx[b]]@W2_r + b2 ---
__global__ void __launch_bounds__(256) out_kernel(const int* __restrict__ idx,
                                                  const float* __restrict__ W2r,
                                                  const float* __restrict__ b2,
                                                  float* __restrict__ out,
                                                  int bcnt) {
    __shared__ __align__(16) float w[512];
    __shared__ float bb[8];
    for (int i = threadIdx.x; i < 512; i += 256) w[i] = W2r[i];
    if (threadIdx.x < 8) bb[threadIdx.x] = b2[threadIdx.x];
    __syncthreads();
    int b = blockIdx.x * 32 + (threadIdx.x >> 3);
    int j = threadIdx.x & 7;
    if (b >= bcnt) return;
    int node = idx[b];
    int s = g_rowstart[node];
    int epos = g_rowstart[node + 1];
    float a0 = 0.f, a1 = 0.f, a2 = 0.f, a3 = 0.f;
    int e = s;
    for (; e + 4 <= epos; e += 4) {
        int s0 = g_srclist[e], s1 = g_srclist[e + 1];
        int s2 = g_srclist[e + 2], s3 = g_srclist[e + 3];
        a0 += g_z[(size_t)s0 * 8 + j];
        a1 += g_z[(size_t)s1 * 8 + j];
        a2 += g_z[(size_t)s2 * 8 + j];
        a3 += g_z[(size_t)s3 * 8 + j];
    }
    for (; e < epos; e++) a0 += g_z[(size_t)g_srclist[e] * 8 + j];
    float acc = ((a0 + a1) + (a2 + a3)) / fmaxf((float)(epos - s), 1.0f);
    const float* hr = g_h + (size_t)node * 64;
    float dot = 0.f;
#pragma unroll
    for (int k = 0; k < 64; k++) dot += hr[k] * w[k * 8 + j];
    out[(size_t)b * 8 + j] = acc + dot + bb[j];
}

// ---------------- launch -----------------------------------------------------
extern "C" void kernel_launch(void* const* d_in, const int* in_sizes, int n_in,
                              void* d_out, int out_size) {
    const float* x    = (const float*)d_in[0];
    const int*   edge = (const int*)d_in[1];   // int32 (JAX x64 disabled)
    const int*   idx  = (const int*)d_in[2];   // int32
    const float* mask = (const float*)d_in[3];
    const float* W1l  = (const float*)d_in[4];
    const float* W1r  = (const float*)d_in[5];
    const float* b1   = (const float*)d_in[6];
    const float* W2l  = (const float*)d_in[7];
    const float* W2r  = (const float*)d_in[8];
    const float* b2   = (const float*)d_in[9];
    float* out = (float*)d_out;

    int n = in_sizes[0] / 128;
    int e = in_sizes[1] / 2;
    int bcnt = in_sizes[2];
    const int* src = edge;
    const int* dst = edge + e;

    int nb = (n + 255) / 256;  // 391 blocks for N=100000

    void* deg_ptr = 0;
    cudaGetSymbolAddress(&deg_ptr, g_deg);

    // fork: FULL CSR chain on side stream first (critical: submit before the
    // NULL-stream gemm so legacy-stream implicit sync can't serialize it)
    cudaEventRecord(g_ev_fork, 0);
    cudaStreamWaitEvent(g_s2, g_ev_fork, 0);

    cudaMemsetAsync(deg_ptr, 0, n * sizeof(int), g_s2);
    hist_kernel<<<(e + 255) / 256, 256, 0, g_s2>>>(dst, e);
    scan_block_kernel<<<nb, 256, 0, g_s2>>>(n);
    add_offsets_kernel<<<nb, 256, 0, g_s2>>>(n, e);
    scatter_kernel<<<(e + 255) / 256, 256, 0, g_s2>>>(src, dst, e);
    cudaEventRecord(g_ev_join, g_s2);

    gemm1_kernel<<<(n + 127) / 128, 256>>>(x, W1l, W1r, n);

    // join: layer1 needs both CSR and gemm1
    cudaStreamWaitEvent(0, g_ev_join, 0);
    layer1_kernel<<<(n + 7) / 8, 256>>>(b1, mask, W2l, n);
    out_kernel<<<(bcnt + 31) / 32, 256>>>(idx, W2r, b2, out, bcnt);
}

// round 16
// speedup vs baseline: 1.3733x; 1.3733x over previous
#include <cuda_runtime.h>
#include <cuda_bf16.h>

// Problem constants (fixed by the reference):
//   N=100000 nodes, E=1600000 edges, IN=128, HID=64, OUT=8, B=16384
// NOTE: reference uses jnp.int64 but JAX x64 is disabled -> edge_index/idx are int32.
#define N_MAX 100000
#define E_MAX 1600000

// ---------------- scratch (device globals; no allocation allowed) ----------
__device__ __align__(256) int   g_deg[N_MAX];
__device__ __align__(256) int   g_rowstart[N_MAX + 1];
__device__ __align__(256) int   g_cursor[N_MAX];
__device__ __align__(256) int   g_srclist[E_MAX];
__device__ __align__(256) int   g_blocksums[512];
__device__ __align__(256) float g_y[(size_t)N_MAX * 128];  // [N][0:64)=x@W1_l, [64:128)=x@W1_r
__device__ __align__(256) float g_h[(size_t)N_MAX * 64];   // layer-1 activations
__device__ __align__(256) float g_z[(size_t)N_MAX * 8];    // h @ W2_l

// ---------------- stream/event for forked capture (created pre-main) --------
static cudaStream_t g_s2 = 0;
static cudaEvent_t  g_ev_fork = 0, g_ev_join = 0;
namespace {
struct StreamInit {
    StreamInit() {
        cudaStreamCreateWithFlags(&g_s2, cudaStreamNonBlocking);
        cudaEventCreateWithFlags(&g_ev_fork, cudaEventDisableTiming);
        cudaEventCreateWithFlags(&g_ev_join, cudaEventDisableTiming);
    }
};
static StreamInit g_stream_init;
}

// ---------------- bf16 split helpers ----------------------------------------
// a = hi + lo + r, |r| ~ 2^-17 |a|. bf16x3 mma drops lo*lo (~2^-18) + r terms.
__device__ __forceinline__ void bsplit(float a, unsigned short& h, unsigned short& l) {
    __nv_bfloat16 hb = __float2bfloat16(a);
    __nv_bfloat16 lb = __float2bfloat16(a - __bfloat162float(hb));
    h = __bfloat16_as_ushort(hb);
    l = __bfloat16_as_ushort(lb);
}
__device__ __forceinline__ unsigned pk(unsigned short lo16, unsigned short hi16) {
    return (unsigned)lo16 | ((unsigned)hi16 << 16);  // low bits = lower-k element
}
__device__ __forceinline__ void mma_bf16(float c[4],
                                         unsigned a0, unsigned a1, unsigned a2, unsigned a3,
                                         unsigned b0, unsigned b1) {
    asm volatile(
        "mma.sync.aligned.m16n8k16.row.col.f32.bf16.bf16.f32 "
        "{%0,%1,%2,%3}, {%4,%5,%6,%7}, {%8,%9}, {%0,%1,%2,%3};"
        : "+f"(c[0]), "+f"(c[1]), "+f"(c[2]), "+f"(c[3])
        : "r"(a0), "r"(a1), "r"(a2), "r"(a3), "r"(b0), "r"(b1));
}

// ---------------- CSR build --------------------------------------------------
__global__ void hist_kernel(const int* __restrict__ dst, int e) {
    int i = blockIdx.x * blockDim.x + threadIdx.x;
    if (i < e) atomicAdd(&g_deg[dst[i]], 1);
}

// per-block exclusive scan over 256 elements
__global__ void __launch_bounds__(256) scan_block_kernel(int n) {
    __shared__ int s[256];
    int i = blockIdx.x * 256 + threadIdx.x;
    int v = (i < n) ? g_deg[i] : 0;
    s[threadIdx.x] = v;
    __syncthreads();
#pragma unroll
    for (int off = 1; off < 256; off <<= 1) {
        int t = 0;
        if ((int)threadIdx.x >= off) t = s[threadIdx.x - off];
        __syncthreads();
        if ((int)threadIdx.x >= off) s[threadIdx.x] += t;
        __syncthreads();
    }
    if (i < n) g_rowstart[i] = s[threadIdx.x] - v;  // exclusive within block
    if (threadIdx.x == 255) g_blocksums[blockIdx.x] = s[255];
}

// add_offsets with inlined block-sum prefix: each block reduces
// g_blocksums[0..blockIdx) itself (<=391 values), then offsets its 256 rows.
__global__ void __launch_bounds__(256) add_offsets_kernel(int n, int e) {
    __shared__ int red[256];
    int b = blockIdx.x;
    int t = threadIdx.x;
    int part = 0;
    for (int i = t; i < b; i += 256) part += g_blocksums[i];
    red[t] = part;
    __syncthreads();
#pragma unroll
    for (int off = 128; off > 0; off >>= 1) {
        if (t < off) red[t] += red[t + off];
        __syncthreads();
    }
    int base = red[0];
    int i = b * 256 + t;
    if (i < n) {
        int r = g_rowstart[i] + base;
        g_rowstart[i] = r;
        g_cursor[i]   = r;
    }
    if (b == 0 && t == 0) g_rowstart[n] = e;
}

__global__ void scatter_kernel(const int* __restrict__ src,
                               const int* __restrict__ dst, int e) {
    int i = blockIdx.x * blockDim.x + threadIdx.x;
    if (i < e) {
        int d = dst[i];
        int p = atomicAdd(&g_cursor[d], 1);
        g_srclist[p] = src[i];
    }
}

// ---------------- GEMM1 (tensor): y = x @ [W1_l | W1_r] ---------------------
// bf16x3 split via mma.sync m16n8k16 (hi*lo + lo*hi + hi*hi), splits hoisted
// into smem-fill as packed bf16x2 pairs (pair = 2 consecutive k).
// 256 threads = 8 warps (2x4), warp tile 64x32 = 4x4 m16n8k16 sub-tiles, kb=32.
// xh stride 20 uints: bank=(20*gid+tig)%32 all-distinct. wh stride 136: bank=
// (8*tig+gid)%32 all-distinct. Both conflict-free.
__global__ void __launch_bounds__(256) gemm1_kernel(const float* __restrict__ x,
                                                    const float* __restrict__ Wl,
                                                    const float* __restrict__ Wr,
                                                    int n) {
    __shared__ unsigned xh[128][20], xlo[128][20];  // row-major x, 16 k-pairs + pad
    __shared__ unsigned wh[16][136], wlo[16][136];  // k-pair major W
    int tid = threadIdx.x;
    int lane = tid & 31;
    int wid = tid >> 5;
    int warp_m = wid >> 2;   // 0..1 -> rows [warp_m*64, +64)
    int warp_n = wid & 3;    // 0..3 -> cols [warp_n*32, +32)
    int gid = lane >> 2;     // groupID (0..7)
    int tig = lane & 3;      // threadID_in_group (0..3)
    int row0 = blockIdx.x * 128;

    float c[4][4][4];
#pragma unroll
    for (int i = 0; i < 4; i++)
#pragma unroll
        for (int j = 0; j < 4; j++)
#pragma unroll
            for (int q = 0; q < 4; q++) c[i][j][q] = 0.0f;

    for (int kb = 0; kb < 128; kb += 32) {
        // x tile: 128 rows x 32 k = 1024 float4, 4 per thread; split+pack pairs
#pragma unroll
        for (int it = 0; it < 4; it++) {
            int i = tid + it * 256;
            int r = i >> 3, c4 = i & 7;
            int gr = row0 + r;
            float4 v = make_float4(0.f, 0.f, 0.f, 0.f);
            if (gr < n) v = *(const float4*)(x + (size_t)gr * 128 + kb + c4 * 4);
            unsigned short hx, lx, hy, ly, hz, lz, hw, lw;
            bsplit(v.x, hx, lx); bsplit(v.y, hy, ly);
            bsplit(v.z, hz, lz); bsplit(v.w, hw, lw);
            xh[r][c4 * 2 + 0] = pk(hx, hy);
            xlo[r][c4 * 2 + 0] = pk(lx, ly);
            xh[r][c4 * 2 + 1] = pk(hz, hw);
            xlo[r][c4 * 2 + 1] = pk(lz, lw);
        }
        // W tile: 32 k x 128 n; thread loads two consecutive-k float4s, packs
        // pairs along k. 512 pair-groups, 2 per thread.
#pragma unroll
        for (int it = 0; it < 2; it++) {
            int i = tid + it * 256;
            int k2 = i >> 5, c4 = i & 31;
            int ka = kb + 2 * k2;
            float4 va, vb;
            if (c4 < 16) {
                va = *(const float4*)(Wl + ka * 64 + c4 * 4);
                vb = *(const float4*)(Wl + (ka + 1) * 64 + c4 * 4);
            } else {
                va = *(const float4*)(Wr + ka * 64 + (c4 - 16) * 4);
                vb = *(const float4*)(Wr + (ka + 1) * 64 + (c4 - 16) * 4);
            }
            float fa[4] = {va.x, va.y, va.z, va.w};
            float fb[4] = {vb.x, vb.y, vb.z, vb.w};
#pragma unroll
            for (int q = 0; q < 4; q++) {
                unsigned short ha, la, hb, lb;
                bsplit(fa[q], ha, la);
                bsplit(fb[q], hb, lb);
                wh[k2][c4 * 4 + q] = pk(ha, hb);   // low bits = lower k
                wlo[k2][c4 * 4 + q] = pk(la, lb);
            }
        }
        __syncthreads();

#pragma unroll
        for (int ks = 0; ks < 2; ks++) {
            int k0p = ks * 8;  // pair-index base (8 pairs = k16 per mma)
            unsigned bh[4][2], bl[4][2];
#pragma unroll
            for (int j = 0; j < 4; j++) {
                int col = warp_n * 32 + j * 8 + gid;
                bh[j][0] = wh[k0p + tig][col];
                bh[j][1] = wh[k0p + tig + 4][col];
                bl[j][0] = wlo[k0p + tig][col];
                bl[j][1] = wlo[k0p + tig + 4][col];
            }
#pragma unroll
            for (int i = 0; i < 4; i++) {
                int ar = warp_m * 64 + i * 16 + gid;
                unsigned ah[4], al[4];
                ah[0] = xh[ar][k0p + tig];
                ah[1] = xh[ar + 8][k0p + tig];
                ah[2] = xh[ar][k0p + tig + 4];
                ah[3] = xh[ar + 8][k0p + tig + 4];
                al[0] = xlo[ar][k0p + tig];
                al[1] = xlo[ar + 8][k0p + tig];
                al[2] = xlo[ar][k0p + tig + 4];
                al[3] = xlo[ar + 8][k0p + tig + 4];
#pragma unroll
                for (int j = 0; j < 4; j++) {
                    mma_bf16(c[i][j], ah[0], ah[1], ah[2], ah[3], bl[j][0], bl[j][1]);
                    mma_bf16(c[i][j], al[0], al[1], al[2], al[3], bh[j][0], bh[j][1]);
                    mma_bf16(c[i][j], ah[0], ah[1], ah[2], ah[3], bh[j][0], bh[j][1]);
                }
            }
        }
        __syncthreads();
    }

    // epilogue: c[i][j] regs -> g_y (combined 128-wide rows)
#pragma unroll
    for (int i = 0; i < 4; i++) {
        int r0 = row0 + warp_m * 64 + i * 16 + gid;
#pragma unroll
        for (int j = 0; j < 4; j++) {
            int col = warp_n * 32 + j * 8 + tig * 2;
            if (r0 < n)
                *(float2*)(g_y + (size_t)r0 * 128 + col) = make_float2(c[i][j][0], c[i][j][1]);
            if (r0 + 8 < n)
                *(float2*)(g_y + (size_t)(r0 + 8) * 128 + col) = make_float2(c[i][j][2], c[i][j][3]);
        }
    }
}

// ---------------- layer 1 combine + z -----------------------------------
// h = dropout(relu(agg/deg + y_r + b1)); z = h @ W2_l (warp butterfly reduce).
// 32 threads per node (float2 per thread), 8 nodes per 256-thread block.
// (R10-proven version.)
__global__ void __launch_bounds__(256) layer1_kernel(const float* __restrict__ b1,
                                                     const float* __restrict__ mask,
                                                     const float* __restrict__ W2l,
                                                     int n) {
    __shared__ __align__(16) float w2[512];
    __shared__ float b1s[64];
    for (int i = threadIdx.x; i < 512; i += 256) w2[i] = W2l[i];
    if (threadIdx.x < 64) b1s[threadIdx.x] = b1[threadIdx.x];
    __syncthreads();

    int node = blockIdx.x * 8 + (threadIdx.x >> 5);
    int lane = threadIdx.x & 31;
    int d = lane * 2;
    if (node >= n) return;
    int s = g_rowstart[node];
    int epos = g_rowstart[node + 1];
    float2 a0 = make_float2(0.f, 0.f), a1 = make_float2(0.f, 0.f);
    float2 a2 = make_float2(0.f, 0.f), a3 = make_float2(0.f, 0.f);
    int e = s;
    for (; e + 4 <= epos; e += 4) {
        int s0 = g_srclist[e], s1 = g_srclist[e + 1];
        int s2 = g_srclist[e + 2], s3 = g_srclist[e + 3];
        float2 v0 = *(const float2*)(g_y + (size_t)s0 * 128 + d);
        float2 v1 = *(const float2*)(g_y + (size_t)s1 * 128 + d);
        float2 v2 = *(const float2*)(g_y + (size_t)s2 * 128 + d);
        float2 v3 = *(const float2*)(g_y + (size_t)s3 * 128 + d);
        a0.x += v0.x; a0.y += v0.y;
        a1.x += v1.x; a1.y += v1.y;
        a2.x += v2.x; a2.y += v2.y;
        a3.x += v3.x; a3.y += v3.y;
    }
    for (; e < epos; e++) {
        float2 v = *(const float2*)(g_y + (size_t)g_srclist[e] * 128 + d);
        a0.x += v.x; a0.y += v.y;
    }
    float sx = (a0.x + a1.x) + (a2.x + a3.x);
    float sy = (a0.y + a1.y) + (a2.y + a3.y);
    float inv = 1.0f / fmaxf((float)(epos - s), 1.0f);
    float2 yr = *(const float2*)(g_y + (size_t)node * 128 + 64 + d);
    float hx = sx * inv + yr.x + b1s[d];
    float hy = sy * inv + yr.y + b1s[d + 1];
    hx = fmaxf(hx, 0.0f);
    hy = fmaxf(hy, 0.0f);
    float2 mk = *(const float2*)(mask + (size_t)node * 64 + d);
    hx = (mk.x > 0.5f) ? hx * 2.0f : 0.0f;
    hy = (mk.y > 0.5f) ? hy * 2.0f : 0.0f;
    *(float2*)(g_h + (size_t)node * 64 + d) = make_float2(hx, hy);

    // z = h @ W2_l : per-lane partials over its 2 dims, butterfly across warp
    float zacc[8];
#pragma unroll
    for (int j = 0; j < 8; j++)
        zacc[j] = hx * w2[d * 8 + j] + hy * w2[(d + 1) * 8 + j];
#pragma unroll
    for (int off = 16; off > 0; off >>= 1)
#pragma unroll
        for (int j = 0; j < 8; j++)
            zacc[j] += __shfl_xor_sync(0xffffffffu, zacc[j], off);
    if (lane == 0) {
        float4* zp = (float4*)(g_z + (size_t)node * 8);
        zp[0] = make_float4(zacc[0], zacc[1], zacc[2], zacc[3]);
        zp[1] = make_float4(zacc[4], zacc[5], zacc[6], zacc[7]);
    }
}

// ---------------- output: out[b] = agg2(idx[b])/deg + h[idx[b]]@W2_r + b2 ---
__global__ void __launch_bounds__(256) out_kernel(const int* __restrict__ idx,
                                                  const float* __restrict__ W2r,
                                                  const float* __restrict__ b2,
                                                  float* __restrict__ out,
                                                  int bcnt) {
    __shared__ __align__(16) float w[512];
    __shared__ float bb[8];
    for (int i = threadIdx.x; i < 512; i += 256) w[i] = W2r[i];
    if (threadIdx.x < 8) bb[threadIdx.x] = b2[threadIdx.x];
    __syncthreads();
    int b = blockIdx.x * 32 + (threadIdx.x >> 3);
    int j = threadIdx.x & 7;
    if (b >= bcnt) return;
    int node = idx[b];
    int s = g_rowstart[node];
    int epos = g_rowstart[node + 1];
    float a0 = 0.f, a1 = 0.f, a2 = 0.f, a3 = 0.f;
    int e = s;
    for (; e + 4 <= epos; e += 4) {
        int s0 = g_srclist[e], s1 = g_srclist[e + 1];
        int s2 = g_srclist[e + 2], s3 = g_srclist[e + 3];
        a0 += g_z[(size_t)s0 * 8 + j];
        a1 += g_z[(size_t)s1 * 8 + j];
        a2 += g_z[(size_t)s2 * 8 + j];
        a3 += g_z[(size_t)s3 * 8 + j];
    }
    for (; e < epos; e++) a0 += g_z[(size_t)g_srclist[e] * 8 + j];
    float acc = ((a0 + a1) + (a2 + a3)) / fmaxf((float)(epos - s), 1.0f);
    const float* hr = g_h + (size_t)node * 64;
    float dot = 0.f;
#pragma unroll
    for (int k = 0; k < 64; k++) dot += hr[k] * w[k * 8 + j];
    out[(size_t)b * 8 + j] = acc + dot + bb[j];
}

// ---------------- launch -----------------------------------------------------
extern "C" void kernel_launch(void* const* d_in, const int* in_sizes, int n_in,
                              void* d_out, int out_size) {
    const float* x    = (const float*)d_in[0];
    const int*   edge = (const int*)d_in[1];   // int32 (JAX x64 disabled)
    const int*   idx  = (const int*)d_in[2];   // int32
    const float* mask = (const float*)d_in[3];
    const float* W1l  = (const float*)d_in[4];
    const float* W1r  = (const float*)d_in[5];
    const float* b1   = (const float*)d_in[6];
    const float* W2l  = (const float*)d_in[7];
    const float* W2r  = (const float*)d_in[8];
    const float* b2   = (const float*)d_in[9];
    float* out = (float*)d_out;

    int n = in_sizes[0] / 128;
    int e = in_sizes[1] / 2;
    int bcnt = in_sizes[2];
    const int* src = edge;
    const int* dst = edge + e;

    int nb = (n + 255) / 256;  // 391 blocks for N=100000

    void* deg_ptr = 0;
    cudaGetSymbolAddress(&deg_ptr, g_deg);

    // fork: CSR chain on side stream, concurrent with gemm1 on main stream
    cudaEventRecord(g_ev_fork, 0);
    cudaStreamWaitEvent(g_s2, g_ev_fork, 0);

    cudaMemsetAsync(deg_ptr, 0, n * sizeof(int), g_s2);
    hist_kernel<<<(e + 255) / 256, 256, 0, g_s2>>>(dst, e);
    scan_block_kernel<<<nb, 256, 0, g_s2>>>(n);
    add_offsets_kernel<<<nb, 256, 0, g_s2>>>(n, e);
    scatter_kernel<<<(e + 255) / 256, 256, 0, g_s2>>>(src, dst, e);
    cudaEventRecord(g_ev_join, g_s2);

    gemm1_kernel<<<(n + 127) / 128, 256>>>(x, W1l, W1r, n);

    // join: layer1 needs both CSR and gemm1
    cudaStreamWaitEvent(0, g_ev_join, 0);
    layer1_kernel<<<(n + 7) / 8, 256>>>(b1, mask, W2l, n);
    out_kernel<<<(bcnt + 31) / 32, 256>>>(idx, W2r, b2, out, bcnt);
}